// round 6
// baseline (speedup 1.0000x reference)
#include <cuda_runtime.h>
#include <math.h>

#define NN 50000
#define EE 600000
#define DD 128
#define HH 8
// SCALE = sqrt(DH) = 4 -> multiply by 0.25f

// -------------------- scratch (device globals; no allocation) --------------------
__device__ float g_Q[(size_t)NN * DD];
__device__ float g_K[(size_t)NN * DD];
__device__ float g_V[(size_t)NN * DD];
__device__ float g_acc[(size_t)NN * DD];     // unnormalized sum of s_exp * V
__device__ float g_ssum[(size_t)NN * HH];    // unnormalized sum of s_exp
__device__ int   g_is64;                     // edge_index dtype (1 = int64, 0 = int32)

// -------------------- helpers --------------------
__device__ __forceinline__ void redAdd4(float* addr, float4 v) {
    asm volatile("red.global.add.v4.f32 [%0], {%1, %2, %3, %4};"
                 :: "l"(addr), "f"(v.x), "f"(v.y), "f"(v.z), "f"(v.w)
                 : "memory");
}

__device__ __forceinline__ int load_idx(const void* ei, int is64, int pos) {
    if (is64) return (int)((const long long*)ei)[pos];
    return ((const int*)ei)[pos];
}

// -------------------- init + dtype probe --------------------
__global__ void init_kernel(const void* ei) {
    int i = blockIdx.x * blockDim.x + threadIdx.x;
    if (i == 0) {
        // Interpret first 64 values as int64; if any out of [0,NN) -> int32 storage.
        const long long* p = (const long long*)ei;
        int ok = 1;
        for (int t = 0; t < 64; t++) {
            long long v = p[t];
            if (v < 0 || v >= NN) { ok = 0; break; }
        }
        g_is64 = ok;
    }
    if (i < NN * DD) g_acc[i] = 0.0f;
    if (i < NN * HH) g_ssum[i] = 0.0f;
}

// -------------------- SGEMM: C = A @ W + b  (128x128x8 tile, 8x8 microtile) ---
// mode: 0 -> C=g_Q, A=Aext(x); 1 -> g_K; 2 -> g_V;
//       3 -> A=g_acc scaled by 1/(g_ssum+1e-8), C=Cext(out)
__global__ __launch_bounds__(256)
void gemm128(const float* __restrict__ Aext,
             const float* __restrict__ W,
             const float* __restrict__ bias,
             float* __restrict__ Cext,
             int mode)
{
    const float* A = (mode == 3) ? g_acc : Aext;
    float* C;
    if (mode == 0) C = g_Q;
    else if (mode == 1) C = g_K;
    else if (mode == 2) C = g_V;
    else C = Cext;

    __shared__ float As[8][132];   // [k][row], padded to kill STS/LDS conflicts
    __shared__ float Bs[8][128];   // [k][col]

    const int tid  = threadIdx.x;
    const int row0 = blockIdx.x * 128;

    // A loader: 128 rows x 8 cols = 1024 floats, 4 per thread
    const int ar = tid >> 1;            // 0..127
    const int ac = (tid & 1) << 2;      // 0 or 4
    // B loader: 8 rows x 128 cols
    const int br = tid >> 5;            // 0..7
    const int bc = (tid & 31) << 2;     // 0..124
    // compute grid: 16x16 threads, 8x8 each
    const int ty = tid >> 4;            // 0..15 (row group)
    const int tx = tid & 15;            // 0..15 (col group)

    const int  gr  = row0 + ar;
    const bool aok = (gr < NN);

    float acc[8][8];
#pragma unroll
    for (int i = 0; i < 8; i++)
#pragma unroll
        for (int j = 0; j < 8; j++) acc[i][j] = 0.0f;

    for (int k0 = 0; k0 < DD; k0 += 8) {
        float4 av = make_float4(0.f, 0.f, 0.f, 0.f);
        if (aok) {
            av = *(const float4*)(A + (size_t)gr * DD + k0 + ac);
            if (mode == 3) {
                // head constant within this float4 (16-aligned head blocks)
                float s = 1.0f / (g_ssum[gr * HH + ((k0 + ac) >> 4)] + 1e-8f);
                av.x *= s; av.y *= s; av.z *= s; av.w *= s;
            }
        }
        As[ac + 0][ar] = av.x;
        As[ac + 1][ar] = av.y;
        As[ac + 2][ar] = av.z;
        As[ac + 3][ar] = av.w;

        *(float4*)&Bs[br][bc] = *(const float4*)(W + (size_t)(k0 + br) * DD + bc);

        __syncthreads();

#pragma unroll
        for (int k = 0; k < 8; k++) {
            float a[8], b[8];
            *(float4*)&a[0] = *(const float4*)&As[k][ty * 8];
            *(float4*)&a[4] = *(const float4*)&As[k][ty * 8 + 4];
            *(float4*)&b[0] = *(const float4*)&Bs[k][tx * 8];
            *(float4*)&b[4] = *(const float4*)&Bs[k][tx * 8 + 4];
#pragma unroll
            for (int i = 0; i < 8; i++)
#pragma unroll
                for (int j = 0; j < 8; j++)
                    acc[i][j] += a[i] * b[j];
        }
        __syncthreads();
    }

    float bb[8];
    *(float4*)&bb[0] = *(const float4*)(bias + tx * 8);
    *(float4*)&bb[4] = *(const float4*)(bias + tx * 8 + 4);

#pragma unroll
    for (int i = 0; i < 8; i++) {
        int r = row0 + ty * 8 + i;
        if (r < NN) {
            float4 o0 = make_float4(acc[i][0] + bb[0], acc[i][1] + bb[1],
                                    acc[i][2] + bb[2], acc[i][3] + bb[3]);
            float4 o1 = make_float4(acc[i][4] + bb[4], acc[i][5] + bb[5],
                                    acc[i][6] + bb[6], acc[i][7] + bb[7]);
            *(float4*)(C + (size_t)r * DD + tx * 8)     = o0;
            *(float4*)(C + (size_t)r * DD + tx * 8 + 4) = o1;
        }
    }
}

// -------------------- fused edge pass: score -> exp -> scatter --------------------
// No max subtraction: softmax is shift-invariant up to the +1e-8 epsilon,
// whose perturbation is <= ~1e-6 relative here (scores bounded ~|6|).
__global__ __launch_bounds__(256)
void edge_fused(const void* __restrict__ ei, const float* __restrict__ ea)
{
    int e = (int)((blockIdx.x * (unsigned)blockDim.x + threadIdx.x) >> 5);
    if (e >= EE) return;
    const int lane = threadIdx.x & 31;
    const int is64 = g_is64;

    const int row = load_idx(ei, is64, e);        // warp-uniform broadcast
    const int col = load_idx(ei, is64, EE + e);

    float4 q = ((const float4*)g_Q)[(size_t)row * 32 + lane];
    float4 k = ((const float4*)g_K)[(size_t)col * 32 + lane];
    float d = q.x * k.x + q.y * k.y + q.z * k.z + q.w * k.w;
    // reduce within 4-lane head groups (DH=16 = 4 lanes x float4)
    d += __shfl_xor_sync(0xffffffffu, d, 1);
    d += __shfl_xor_sync(0xffffffffu, d, 2);

    const float score = d * 0.25f + ea[e];
    const float sexp  = __expf(score);

    const int h = lane >> 2;
    if ((lane & 3) == 0) atomicAdd(&g_ssum[row * HH + h], sexp);

    float4 v = ((const float4*)g_V)[(size_t)col * 32 + lane];
    float4 o = make_float4(v.x * sexp, v.y * sexp, v.z * sexp, v.w * sexp);
    redAdd4(g_acc + (size_t)row * DD + lane * 4, o);
}

// -------------------- launch --------------------
extern "C" void kernel_launch(void* const* d_in, const int* in_sizes, int n_in,
                              void* d_out, int out_size)
{
    const float* x  = (const float*)d_in[0];
    const void*  ei = d_in[1];
    const float* ea = (const float*)d_in[2];
    const float* Wq = (const float*)d_in[3];
    const float* bq = (const float*)d_in[4];
    const float* Wk = (const float*)d_in[5];
    const float* bk = (const float*)d_in[6];
    const float* Wv = (const float*)d_in[7];
    const float* bv = (const float*)d_in[8];
    const float* Wo = (const float*)d_in[9];
    const float* bo = (const float*)d_in[10];
    float* out = (float*)d_out;

    const int gemm_blocks = (NN + 127) / 128;
    const int edge_blocks = (EE * 32 + 255) / 256;

    init_kernel<<<(NN * DD + 255) / 256, 256>>>(ei);
    gemm128<<<gemm_blocks, 256>>>(x, Wq, bq, nullptr, 0);
    gemm128<<<gemm_blocks, 256>>>(x, Wk, bk, nullptr, 1);
    gemm128<<<gemm_blocks, 256>>>(x, Wv, bv, nullptr, 2);
    edge_fused<<<edge_blocks, 256>>>(ei, ea);
    gemm128<<<gemm_blocks, 256>>>(nullptr, Wo, bo, out, 3);
}

// round 7
// speedup vs baseline: 1.2338x; 1.2338x over previous
#include <cuda_runtime.h>
#include <math.h>

#define NN 50000
#define EE 600000
#define DD 128
#define HH 8
// SCALE = sqrt(DH) = 4 -> multiply by 0.25f

// -------------------- scratch (device globals; no allocation) --------------------
__device__ float g_Q[(size_t)NN * DD];
__device__ float g_K[(size_t)NN * DD];
__device__ float g_V[(size_t)NN * DD];
__device__ float g_acc[(size_t)NN * DD];     // unnormalized sum of s_exp * V
__device__ float g_ssum[(size_t)NN * HH];    // unnormalized sum of s_exp
__device__ int   g_is64;                     // edge_index dtype (1 = int64, 0 = int32)

// -------------------- helpers --------------------
__device__ __forceinline__ void redAdd4(float* addr, float4 v) {
    asm volatile("red.global.add.v4.f32 [%0], {%1, %2, %3, %4};"
                 :: "l"(addr), "f"(v.x), "f"(v.y), "f"(v.z), "f"(v.w)
                 : "memory");
}

__device__ __forceinline__ int load_idx(const void* ei, int is64, int pos) {
    if (is64) return (int)((const long long*)ei)[pos];
    return ((const int*)ei)[pos];
}

// ---- packed f32x2 math (sm_100+): 2 FMAs per issue slot ----
__device__ __forceinline__ unsigned long long pack2(float lo, float hi) {
    unsigned long long r;
    asm("mov.b64 %0, {%1, %2};" : "=l"(r) : "f"(lo), "f"(hi));
    return r;
}
__device__ __forceinline__ void unpack2(unsigned long long v, float& lo, float& hi) {
    asm("mov.b64 {%0, %1}, %2;" : "=f"(lo), "=f"(hi) : "l"(v));
}
__device__ __forceinline__ void fma2(unsigned long long& d,
                                     unsigned long long a, unsigned long long b) {
    asm("fma.rn.f32x2 %0, %1, %2, %0;" : "+l"(d) : "l"(a), "l"(b));
}

// -------------------- init + dtype probe --------------------
__global__ void init_kernel(const void* ei) {
    int i = blockIdx.x * blockDim.x + threadIdx.x;
    if (i == 0) {
        const long long* p = (const long long*)ei;
        int ok = 1;
        for (int t = 0; t < 64; t++) {
            long long v = p[t];
            if (v < 0 || v >= NN) { ok = 0; break; }
        }
        g_is64 = ok;
    }
    if (i < NN * DD) g_acc[i] = 0.0f;
    if (i < NN * HH) g_ssum[i] = 0.0f;
}

// -------------------- SGEMM: C = A @ W + b --------------------
// BM=64, BN=128, BK=16, 256 threads. Microtile 8(i) x 4(j) per thread,
// computed as 4 f32x2 row-pairs x 4 cols via fma.rn.f32x2.
// mode: 0 -> C=g_Q, A=x; 1 -> g_K; 2 -> g_V;
//       3 -> A=g_acc scaled by 1/(g_ssum+1e-8), C=Cext(out)
__global__ __launch_bounds__(256)
void gemm128(const float* __restrict__ Aext,
             const float* __restrict__ W,
             const float* __restrict__ bias,
             float* __restrict__ Cext,
             int mode)
{
    const float* A = (mode == 3) ? g_acc : Aext;
    float* C;
    if (mode == 0) C = g_Q;
    else if (mode == 1) C = g_K;
    else if (mode == 2) C = g_V;
    else C = Cext;

    __shared__ float As[16][68];    // [k][row]; pad 68 keeps 16B alignment of row pairs
    __shared__ float Bs[16][128];   // [k][col]

    const int tid  = threadIdx.x;
    const int row0 = blockIdx.x * 64;

    const int arow = tid >> 2;          // 0..63
    const int acol = (tid & 3) << 2;    // 0,4,8,12
    const int brow = tid >> 5;          // 0..7
    const int bcol = (tid & 31) << 2;   // 0..124
    const int tr   = tid >> 5;          // warp id: rows tr*8 .. tr*8+7
    const int tc   = tid & 31;          // lane: cols tc*4 .. tc*4+3

    // acc2[p][j]: rows (2p, 2p+1) packed as f32x2, col j
    unsigned long long acc2[4][4];
    const unsigned long long z2 = pack2(0.0f, 0.0f);
#pragma unroll
    for (int p = 0; p < 4; p++)
#pragma unroll
        for (int j = 0; j < 4; j++) acc2[p][j] = z2;

    const int  gr  = row0 + arow;
    const bool aok = (gr < NN);

    for (int k0 = 0; k0 < DD; k0 += 16) {
        float4 av = make_float4(0.f, 0.f, 0.f, 0.f);
        if (aok) {
            av = *(const float4*)(A + (size_t)gr * DD + k0 + acol);
            if (mode == 3) {
                // head constant within this float4 (16-aligned head blocks)
                float s = 1.0f / (g_ssum[gr * HH + ((k0 + acol) >> 4)] + 1e-8f);
                av.x *= s; av.y *= s; av.z *= s; av.w *= s;
            }
        }
        As[acol + 0][arow] = av.x;
        As[acol + 1][arow] = av.y;
        As[acol + 2][arow] = av.z;
        As[acol + 3][arow] = av.w;

        float4 b0 = *(const float4*)(W + (size_t)(k0 + brow) * DD + bcol);
        float4 b1 = *(const float4*)(W + (size_t)(k0 + brow + 8) * DD + bcol);
        *(float4*)&Bs[brow][bcol]     = b0;
        *(float4*)&Bs[brow + 8][bcol] = b1;

        __syncthreads();

#pragma unroll
        for (int k = 0; k < 16; k++) {
            // a row-pairs: contiguous in As -> 2x LDS.128 = 4 f32x2 pairs (warp-broadcast)
            ulonglong2 a01 = *(const ulonglong2*)&As[k][tr * 8];      // (a0,a1),(a2,a3)
            ulonglong2 a23 = *(const ulonglong2*)&As[k][tr * 8 + 4];  // (a4,a5),(a6,a7)
            float4 bv = *(const float4*)&Bs[k][tc * 4];
            unsigned long long bd0 = pack2(bv.x, bv.x);
            unsigned long long bd1 = pack2(bv.y, bv.y);
            unsigned long long bd2 = pack2(bv.z, bv.z);
            unsigned long long bd3 = pack2(bv.w, bv.w);

            fma2(acc2[0][0], a01.x, bd0); fma2(acc2[0][1], a01.x, bd1);
            fma2(acc2[0][2], a01.x, bd2); fma2(acc2[0][3], a01.x, bd3);
            fma2(acc2[1][0], a01.y, bd0); fma2(acc2[1][1], a01.y, bd1);
            fma2(acc2[1][2], a01.y, bd2); fma2(acc2[1][3], a01.y, bd3);
            fma2(acc2[2][0], a23.x, bd0); fma2(acc2[2][1], a23.x, bd1);
            fma2(acc2[2][2], a23.x, bd2); fma2(acc2[2][3], a23.x, bd3);
            fma2(acc2[3][0], a23.y, bd0); fma2(acc2[3][1], a23.y, bd1);
            fma2(acc2[3][2], a23.y, bd2); fma2(acc2[3][3], a23.y, bd3);
        }
        __syncthreads();
    }

    float4 bb = *(const float4*)(bias + tc * 4);
#pragma unroll
    for (int p = 0; p < 4; p++) {
        float lo[4], hi[4];
#pragma unroll
        for (int j = 0; j < 4; j++) unpack2(acc2[p][j], lo[j], hi[j]);
        int r0 = row0 + tr * 8 + 2 * p;
        if (r0 < NN) {
            float4 o = make_float4(lo[0] + bb.x, lo[1] + bb.y, lo[2] + bb.z, lo[3] + bb.w);
            *(float4*)(C + (size_t)r0 * DD + tc * 4) = o;
        }
        if (r0 + 1 < NN) {
            float4 o = make_float4(hi[0] + bb.x, hi[1] + bb.y, hi[2] + bb.z, hi[3] + bb.w);
            *(float4*)(C + (size_t)(r0 + 1) * DD + tc * 4) = o;
        }
    }
}

// -------------------- fused edge pass: score -> exp -> scatter --------------------
// No max subtraction: softmax is shift-invariant up to the +1e-8 epsilon,
// whose perturbation is <= ~1e-6 relative here (scores bounded ~|6|).
__global__ __launch_bounds__(256)
void edge_fused(const void* __restrict__ ei, const float* __restrict__ ea)
{
    int e = (int)((blockIdx.x * (unsigned)blockDim.x + threadIdx.x) >> 5);
    if (e >= EE) return;
    const int lane = threadIdx.x & 31;
    const int is64 = g_is64;

    const int row = load_idx(ei, is64, e);        // warp-uniform broadcast
    const int col = load_idx(ei, is64, EE + e);

    float4 q = ((const float4*)g_Q)[(size_t)row * 32 + lane];
    float4 k = ((const float4*)g_K)[(size_t)col * 32 + lane];
    float d = q.x * k.x + q.y * k.y + q.z * k.z + q.w * k.w;
    // reduce within 4-lane head groups (DH=16 = 4 lanes x float4)
    d += __shfl_xor_sync(0xffffffffu, d, 1);
    d += __shfl_xor_sync(0xffffffffu, d, 2);

    const float score = d * 0.25f + ea[e];
    const float sexp  = __expf(score);

    const int h = lane >> 2;
    if ((lane & 3) == 0) atomicAdd(&g_ssum[row * HH + h], sexp);

    float4 v = ((const float4*)g_V)[(size_t)col * 32 + lane];
    float4 o = make_float4(v.x * sexp, v.y * sexp, v.z * sexp, v.w * sexp);
    redAdd4(g_acc + (size_t)row * DD + lane * 4, o);
}

// -------------------- launch --------------------
extern "C" void kernel_launch(void* const* d_in, const int* in_sizes, int n_in,
                              void* d_out, int out_size)
{
    const float* x  = (const float*)d_in[0];
    const void*  ei = d_in[1];
    const float* ea = (const float*)d_in[2];
    const float* Wq = (const float*)d_in[3];
    const float* bq = (const float*)d_in[4];
    const float* Wk = (const float*)d_in[5];
    const float* bk = (const float*)d_in[6];
    const float* Wv = (const float*)d_in[7];
    const float* bv = (const float*)d_in[8];
    const float* Wo = (const float*)d_in[9];
    const float* bo = (const float*)d_in[10];
    float* out = (float*)d_out;

    const int gemm_blocks = (NN + 63) / 64;
    const int edge_blocks = (EE * 32 + 255) / 256;

    init_kernel<<<(NN * DD + 255) / 256, 256>>>(ei);
    gemm128<<<gemm_blocks, 256>>>(x, Wq, bq, nullptr, 0);
    gemm128<<<gemm_blocks, 256>>>(x, Wk, bk, nullptr, 1);
    gemm128<<<gemm_blocks, 256>>>(x, Wv, bv, nullptr, 2);
    edge_fused<<<edge_blocks, 256>>>(ei, ea);
    gemm128<<<gemm_blocks, 256>>>(nullptr, Wo, bo, out, 3);
}

// round 10
// speedup vs baseline: 1.4363x; 1.1642x over previous
#include <cuda_runtime.h>
#include <cuda_bf16.h>
#include <math.h>
#include <stdint.h>

#define NN 50000
#define EE 600000
#define DD 128
#define HH 8
// SCALE = sqrt(DH) = 4 -> multiply by 0.25f

// -------------------- scratch (device globals; no allocation) --------------------
__device__ float g_Q[(size_t)NN * DD];
__device__ float g_K[(size_t)NN * DD];
__device__ float g_V[(size_t)NN * DD];
__device__ float g_acc[(size_t)NN * DD];            // unnormalized sum of s_exp * V
__device__ float g_ssum[(size_t)NN * HH];           // unnormalized sum of s_exp
__device__ __nv_bfloat16 g_xhi[(size_t)NN * DD];    // A operand hi (x, later normalized acc)
__device__ __nv_bfloat16 g_xlo[(size_t)NN * DD];    // A operand lo
__device__ __nv_bfloat16 g_whi[4 * DD * DD];        // W^T hi: [mat][n][k]
__device__ __nv_bfloat16 g_wlo[4 * DD * DD];        // W^T lo
__device__ int   g_is64;

// -------------------- helpers --------------------
__device__ __forceinline__ uint32_t smem_u32(const void* p) {
    uint32_t a;
    asm("{ .reg .u64 t; cvta.to.shared.u64 t, %1; cvt.u32.u64 %0, t; }" : "=r"(a) : "l"(p));
    return a;
}
__device__ __forceinline__ void redAdd4(float* addr, float4 v) {
    asm volatile("red.global.add.v4.f32 [%0], {%1, %2, %3, %4};"
                 :: "l"(addr), "f"(v.x), "f"(v.y), "f"(v.z), "f"(v.w) : "memory");
}
__device__ __forceinline__ int load_idx(const void* ei, int is64, int pos) {
    if (is64) return (int)((const long long*)ei)[pos];
    return ((const int*)ei)[pos];
}
__device__ __forceinline__ void ldsm_x4(uint32_t& r0, uint32_t& r1, uint32_t& r2, uint32_t& r3,
                                        uint32_t addr) {
    asm volatile("ldmatrix.sync.aligned.m8n8.x4.shared.b16 {%0,%1,%2,%3}, [%4];"
                 : "=r"(r0), "=r"(r1), "=r"(r2), "=r"(r3) : "r"(addr));
}
__device__ __forceinline__ void ldsm_x2(uint32_t& r0, uint32_t& r1, uint32_t addr) {
    asm volatile("ldmatrix.sync.aligned.m8n8.x2.shared.b16 {%0,%1}, [%2];"
                 : "=r"(r0), "=r"(r1) : "r"(addr));
}
__device__ __forceinline__ void mma16816(float* d, const uint32_t* a, const uint32_t* b) {
    asm volatile("mma.sync.aligned.m16n8k16.row.col.f32.bf16.bf16.f32 "
                 "{%0,%1,%2,%3}, {%4,%5,%6,%7}, {%8,%9}, {%0,%1,%2,%3};"
                 : "+f"(d[0]), "+f"(d[1]), "+f"(d[2]), "+f"(d[3])
                 : "r"(a[0]), "r"(a[1]), "r"(a[2]), "r"(a[3]), "r"(b[0]), "r"(b[1]));
}

// -------------------- init + dtype probe --------------------
__global__ void init_kernel(const void* ei) {
    int i = blockIdx.x * blockDim.x + threadIdx.x;
    if (i == 0) {
        const long long* p = (const long long*)ei;
        int ok = 1;
        for (int t = 0; t < 64; t++) {
            long long v = p[t];
            if (v < 0 || v >= NN) { ok = 0; break; }
        }
        g_is64 = ok;
    }
    if (i < NN * DD) g_acc[i] = 0.0f;
    if (i < NN * HH) g_ssum[i] = 0.0f;
}

// -------------------- fp32 -> bf16 hi/lo split of x --------------------
__global__ void convert_x(const float* __restrict__ x) {
    int i = blockIdx.x * blockDim.x + threadIdx.x;
    if (i >= NN * DD) return;
    float f = x[i];
    __nv_bfloat16 hi = __float2bfloat16(f);
    __nv_bfloat16 lo = __float2bfloat16(f - __bfloat162float(hi));
    g_xhi[i] = hi;
    g_xlo[i] = lo;
}

// -------------------- W -> W^T bf16 hi/lo (4 matrices) --------------------
__global__ void convert_w(const float* __restrict__ W0, const float* __restrict__ W1,
                          const float* __restrict__ W2, const float* __restrict__ W3) {
    int i = blockIdx.x * blockDim.x + threadIdx.x;
    if (i >= 4 * DD * DD) return;
    int w = i >> 14;
    int n = (i >> 7) & 127;
    int k = i & 127;
    const float* W = (w == 0) ? W0 : (w == 1) ? W1 : (w == 2) ? W2 : W3;
    float f = W[k * DD + n];                      // transpose: B[n][k] = W[k][n]
    __nv_bfloat16 hi = __float2bfloat16(f);
    __nv_bfloat16 lo = __float2bfloat16(f - __bfloat162float(hi));
    g_whi[i] = hi;
    g_wlo[i] = lo;
}

// -------------------- normalized acc -> bf16 hi/lo (reuse g_xhi/g_xlo) ------
__global__ void convert_acc() {
    int i = blockIdx.x * blockDim.x + threadIdx.x;
    if (i >= NN * DD) return;
    int row = i >> 7;
    int h = (i >> 4) & 7;
    float f = g_acc[i] * (1.0f / (g_ssum[row * HH + h] + 1e-8f));
    __nv_bfloat16 hi = __float2bfloat16(f);
    __nv_bfloat16 lo = __float2bfloat16(f - __bfloat162float(hi));
    g_xhi[i] = hi;
    g_xlo[i] = lo;
}

// -------------------- HMMA GEMM: C = (Ahi+Alo) @ (Bhi+Blo)^T + bias --------
// CTA tile 128(M) x 128(N) x 128(K). 8 warps (2x4), warp tile 64x32.
// bf16-split: D = Ahi*Bhi + Ahi*Blo + Alo*Bhi (lo*lo dropped, ~2^-18).
#define LDA 136                        // bf16 stride; 272B rows -> conflict-free ldmatrix
#define TILE_ELEMS (128 * LDA)         // 17408 bf16 = 34816 B per operand tile
#define SME_BIAS_OFF (4 * TILE_ELEMS)  // floats after the 4 bf16 tiles
#define SME_TOT (4 * TILE_ELEMS * 2 + 512)

__global__ __launch_bounds__(256, 1)
void tgemm(const __nv_bfloat16* __restrict__ Ahi, const __nv_bfloat16* __restrict__ Alo,
           const __nv_bfloat16* __restrict__ Bhi, const __nv_bfloat16* __restrict__ Blo,
           const float* __restrict__ bias, float* __restrict__ C)
{
    extern __shared__ __nv_bfloat16 sm[];
    __nv_bfloat16* sAhi = sm;
    __nv_bfloat16* sAlo = sm + TILE_ELEMS;
    __nv_bfloat16* sBhi = sm + 2 * TILE_ELEMS;
    __nv_bfloat16* sBlo = sm + 3 * TILE_ELEMS;
    float* sbias = (float*)(sm + SME_BIAS_OFF);

    const int tid  = threadIdx.x;
    const int row0 = blockIdx.x * 128;

    // ---- load operand tiles: 128 rows x 16 chunks of 8 bf16 each ----
    const uint4 zero4 = make_uint4(0, 0, 0, 0);
#pragma unroll
    for (int t = tid; t < 2048; t += 256) {
        int r  = t >> 4;
        int c8 = (t & 15) << 3;
        bool aok = (row0 + r) < NN;
        uint4 va = aok ? *(const uint4*)(Ahi + (size_t)(row0 + r) * DD + c8) : zero4;
        uint4 vb = aok ? *(const uint4*)(Alo + (size_t)(row0 + r) * DD + c8) : zero4;
        *(uint4*)(sAhi + r * LDA + c8) = va;
        *(uint4*)(sAlo + r * LDA + c8) = vb;
        uint4 wa = *(const uint4*)(Bhi + (size_t)r * DD + c8);
        uint4 wb = *(const uint4*)(Blo + (size_t)r * DD + c8);
        *(uint4*)(sBhi + r * LDA + c8) = wa;
        *(uint4*)(sBlo + r * LDA + c8) = wb;
    }
    if (tid < 128) sbias[tid] = bias[tid];
    __syncthreads();

    const int wid  = tid >> 5;
    const int lane = tid & 31;
    const int wm = (wid >> 2) * 64;    // warp M offset (0 or 64)
    const int wn = (wid & 3) * 32;     // warp N offset (0,32,64,96)

    // ldmatrix lane addressing
    const int sub = lane >> 3;         // 0..3
    const int r8  = lane & 7;
    const int aRow = r8 + (sub & 1) * 8;      // row within 16-row tile
    const int aKof = (sub >> 1) * 8;          // k sub-block
    const int bl  = lane & 15;
    const int bRow = bl & 7;                  // n within 8-row tile
    const int bKof = (bl >> 3) * 8;

    const uint32_t smb = smem_u32(sm);
    const uint32_t aHiB = smb;
    const uint32_t bHiB = smb + 2 * TILE_ELEMS * 2;

    float acc[4][4][4];
#pragma unroll
    for (int mt = 0; mt < 4; mt++)
#pragma unroll
        for (int nt = 0; nt < 4; nt++)
#pragma unroll
            for (int j = 0; j < 4; j++) acc[mt][nt][j] = 0.0f;

#pragma unroll
    for (int ks = 0; ks < 8; ks++) {
        const int k0 = ks * 16;
        uint32_t bhi[4][2], blo[4][2];
#pragma unroll
        for (int nt = 0; nt < 4; nt++) {
            uint32_t off = (uint32_t)((wn + nt * 8 + bRow) * LDA + k0 + bKof) * 2;
            ldsm_x2(bhi[nt][0], bhi[nt][1], bHiB + off);
            ldsm_x2(blo[nt][0], blo[nt][1], bHiB + TILE_ELEMS * 2 + off);
        }
        uint32_t ahi[4][4], alo[4][4];
#pragma unroll
        for (int mt = 0; mt < 4; mt++) {
            uint32_t off = (uint32_t)((wm + mt * 16 + aRow) * LDA + k0 + aKof) * 2;
            ldsm_x4(ahi[mt][0], ahi[mt][1], ahi[mt][2], ahi[mt][3], aHiB + off);
            ldsm_x4(alo[mt][0], alo[mt][1], alo[mt][2], alo[mt][3],
                    aHiB + TILE_ELEMS * 2 + off);
        }
#pragma unroll
        for (int mt = 0; mt < 4; mt++)
#pragma unroll
            for (int nt = 0; nt < 4; nt++) {
                mma16816(acc[mt][nt], ahi[mt], bhi[nt]);
                mma16816(acc[mt][nt], ahi[mt], blo[nt]);
                mma16816(acc[mt][nt], alo[mt], bhi[nt]);
            }
    }

    // ---- epilogue: d frag c0=(g,2t) c1=(g,2t+1) c2=(g+8,2t) c3=(g+8,2t+1) ----
    const int g  = lane >> 2;
    const int t4 = lane & 3;
#pragma unroll
    for (int mt = 0; mt < 4; mt++) {
#pragma unroll
        for (int nt = 0; nt < 4; nt++) {
            int col = wn + nt * 8 + t4 * 2;
            float b0 = sbias[col], b1 = sbias[col + 1];
            int gr0 = row0 + wm + mt * 16 + g;
            if (gr0 < NN) {
                float2 o = make_float2(acc[mt][nt][0] + b0, acc[mt][nt][1] + b1);
                *(float2*)(C + (size_t)gr0 * DD + col) = o;
            }
            int gr1 = gr0 + 8;
            if (gr1 < NN) {
                float2 o = make_float2(acc[mt][nt][2] + b0, acc[mt][nt][3] + b1);
                *(float2*)(C + (size_t)gr1 * DD + col) = o;
            }
        }
    }
}

// -------------------- fused edge pass: score -> exp -> scatter --------------------
// No max subtraction: softmax is shift-invariant up to the +1e-8 epsilon,
// whose perturbation is <= ~1e-6 relative here (scores bounded ~|6|).
__global__ __launch_bounds__(256)
void edge_fused(const void* __restrict__ ei, const float* __restrict__ ea)
{
    int e = (int)((blockIdx.x * (unsigned)blockDim.x + threadIdx.x) >> 5);
    if (e >= EE) return;
    const int lane = threadIdx.x & 31;
    const int is64 = g_is64;

    const int row = load_idx(ei, is64, e);        // warp-uniform broadcast
    const int col = load_idx(ei, is64, EE + e);

    float4 q = ((const float4*)g_Q)[(size_t)row * 32 + lane];
    float4 k = ((const float4*)g_K)[(size_t)col * 32 + lane];
    float d = q.x * k.x + q.y * k.y + q.z * k.z + q.w * k.w;
    d += __shfl_xor_sync(0xffffffffu, d, 1);
    d += __shfl_xor_sync(0xffffffffu, d, 2);

    const float score = d * 0.25f + ea[e];
    const float sexp  = __expf(score);

    const int h = lane >> 2;
    if ((lane & 3) == 0) atomicAdd(&g_ssum[row * HH + h], sexp);

    float4 v = ((const float4*)g_V)[(size_t)col * 32 + lane];
    float4 o = make_float4(v.x * sexp, v.y * sexp, v.z * sexp, v.w * sexp);
    redAdd4(g_acc + (size_t)row * DD + lane * 4, o);
}

// -------------------- launch --------------------
extern "C" void kernel_launch(void* const* d_in, const int* in_sizes, int n_in,
                              void* d_out, int out_size)
{
    const float* x  = (const float*)d_in[0];
    const void*  ei = d_in[1];
    const float* ea = (const float*)d_in[2];
    const float* Wq = (const float*)d_in[3];
    const float* bq = (const float*)d_in[4];
    const float* Wk = (const float*)d_in[5];
    const float* bk = (const float*)d_in[6];
    const float* Wv = (const float*)d_in[7];
    const float* bv = (const float*)d_in[8];
    const float* Wo = (const float*)d_in[9];
    const float* bo = (const float*)d_in[10];
    float* out = (float*)d_out;

    static int smem_set = 0;
    if (!smem_set) {
        cudaFuncSetAttribute(tgemm, cudaFuncAttributeMaxDynamicSharedMemorySize, SME_TOT);
        smem_set = 1;
    }

    __nv_bfloat16 *xhi, *xlo, *whi, *wlo;
    float *Qp, *Kp, *Vp;
    cudaGetSymbolAddress((void**)&xhi, g_xhi);
    cudaGetSymbolAddress((void**)&xlo, g_xlo);
    cudaGetSymbolAddress((void**)&whi, g_whi);
    cudaGetSymbolAddress((void**)&wlo, g_wlo);
    cudaGetSymbolAddress((void**)&Qp, g_Q);
    cudaGetSymbolAddress((void**)&Kp, g_K);
    cudaGetSymbolAddress((void**)&Vp, g_V);

    const int gemm_blocks = (NN + 127) / 128;
    const int edge_blocks = (EE * 32 + 255) / 256;

    init_kernel<<<(NN * DD + 255) / 256, 256>>>(ei);
    convert_x<<<(NN * DD + 255) / 256, 256>>>(x);
    convert_w<<<(4 * DD * DD + 255) / 256, 256>>>(Wq, Wk, Wv, Wo);

    tgemm<<<gemm_blocks, 256, SME_TOT>>>(xhi, xlo, whi + 0 * DD * DD, wlo + 0 * DD * DD, bq, Qp);
    tgemm<<<gemm_blocks, 256, SME_TOT>>>(xhi, xlo, whi + 1 * DD * DD, wlo + 1 * DD * DD, bk, Kp);
    tgemm<<<gemm_blocks, 256, SME_TOT>>>(xhi, xlo, whi + 2 * DD * DD, wlo + 2 * DD * DD, bv, Vp);

    edge_fused<<<edge_blocks, 256>>>(ei, ea);
    convert_acc<<<(NN * DD + 255) / 256, 256>>>();

    tgemm<<<gemm_blocks, 256, SME_TOT>>>(xhi, xlo, whi + 3 * DD * DD, wlo + 3 * DD * DD, bo, out);
}

// round 12
// speedup vs baseline: 2.0590x; 1.4335x over previous
#include <cuda_runtime.h>
#include <cuda_bf16.h>
#include <math.h>
#include <stdint.h>

#define NN 50000
#define EE 600000
#define DD 128
#define HH 8
// SCALE = sqrt(DH) = 4 -> multiply by 0.25f

// -------------------- scratch (device globals; no allocation) --------------------
__device__ float g_Q[(size_t)NN * DD];
__device__ float g_K[(size_t)NN * DD];
__device__ float g_V[(size_t)NN * DD];
__device__ __nv_bfloat16 g_xhi[(size_t)NN * DD];    // A operand hi (x, later attn-out)
__device__ __nv_bfloat16 g_xlo[(size_t)NN * DD];    // A operand lo
__device__ __nv_bfloat16 g_whi[4 * DD * DD];        // W^T hi: [mat][n][k]
__device__ __nv_bfloat16 g_wlo[4 * DD * DD];        // W^T lo
__device__ int   g_counts[NN];
__device__ int   g_pos[EE];
__device__ int   g_rowstart[NN + 1];
__device__ int   g_bsum[64];
__device__ int   g_bscan[64];
__device__ int2  g_edges[EE];                       // {col, ea bits} sorted by row
__device__ int   g_is64;

// -------------------- helpers --------------------
__device__ __forceinline__ uint32_t smem_u32(const void* p) {
    uint32_t a;
    asm("{ .reg .u64 t; cvta.to.shared.u64 t, %1; cvt.u32.u64 %0, t; }" : "=r"(a) : "l"(p));
    return a;
}
__device__ __forceinline__ int load_idx(const void* ei, int is64, int pos) {
    if (is64) return (int)((const long long*)ei)[pos];
    return ((const int*)ei)[pos];
}
__device__ __forceinline__ void ldsm_x4(uint32_t& r0, uint32_t& r1, uint32_t& r2, uint32_t& r3,
                                        uint32_t addr) {
    asm volatile("ldmatrix.sync.aligned.m8n8.x4.shared.b16 {%0,%1,%2,%3}, [%4];"
                 : "=r"(r0), "=r"(r1), "=r"(r2), "=r"(r3) : "r"(addr));
}
__device__ __forceinline__ void ldsm_x2(uint32_t& r0, uint32_t& r1, uint32_t addr) {
    asm volatile("ldmatrix.sync.aligned.m8n8.x2.shared.b16 {%0,%1}, [%2];"
                 : "=r"(r0), "=r"(r1) : "r"(addr));
}
__device__ __forceinline__ void mma16816(float* d, const uint32_t* a, const uint32_t* b) {
    asm volatile("mma.sync.aligned.m16n8k16.row.col.f32.bf16.bf16.f32 "
                 "{%0,%1,%2,%3}, {%4,%5,%6,%7}, {%8,%9}, {%0,%1,%2,%3};"
                 : "+f"(d[0]), "+f"(d[1]), "+f"(d[2]), "+f"(d[3])
                 : "r"(a[0]), "r"(a[1]), "r"(a[2]), "r"(a[3]), "r"(b[0]), "r"(b[1]));
}
__device__ __forceinline__ uint32_t pack_bf2(__nv_bfloat16 a, __nv_bfloat16 b) {
    return (uint32_t)__bfloat16_as_ushort(a) | ((uint32_t)__bfloat16_as_ushort(b) << 16);
}

// -------------------- probe dtype + zero counts --------------------
__global__ void probe_zero(const void* ei) {
    int i = blockIdx.x * blockDim.x + threadIdx.x;
    if (i == 0) {
        const long long* p = (const long long*)ei;
        int ok = 1;
        for (int t = 0; t < 64; t++) {
            long long v = p[t];
            if (v < 0 || v >= NN) { ok = 0; break; }
        }
        g_is64 = ok;
    }
    if (i < NN) g_counts[i] = 0;
}

// -------------------- CSR build --------------------
__global__ void hist_kernel(const void* __restrict__ ei) {
    int e = blockIdx.x * blockDim.x + threadIdx.x;
    if (e >= EE) return;
    int row = load_idx(ei, g_is64, e);
    g_pos[e] = atomicAdd(&g_counts[row], 1);
}

__global__ __launch_bounds__(1024) void scan1_kernel() {
    __shared__ int s[1024];
    int tid = threadIdx.x;
    int gid = blockIdx.x * 1024 + tid;
    int v = (gid < NN) ? g_counts[gid] : 0;
    s[tid] = v;
    __syncthreads();
#pragma unroll
    for (int off = 1; off < 1024; off <<= 1) {
        int t = (tid >= off) ? s[tid - off] : 0;
        __syncthreads();
        s[tid] += t;
        __syncthreads();
    }
    if (gid < NN) g_rowstart[gid] = s[tid] - v;    // exclusive within block
    if (tid == 1023) g_bsum[blockIdx.x] = s[1023];
}

__global__ void scan2_kernel() {
    __shared__ int s[64];
    int tid = threadIdx.x;
    int v = (tid < 49) ? g_bsum[tid] : 0;
    s[tid] = v;
    __syncthreads();
#pragma unroll
    for (int off = 1; off < 64; off <<= 1) {
        int t = (tid >= off) ? s[tid - off] : 0;
        __syncthreads();
        s[tid] += t;
        __syncthreads();
    }
    g_bscan[tid] = s[tid] - v;                      // exclusive block offsets
}

__global__ void scan3_kernel() {
    int i = blockIdx.x * blockDim.x + threadIdx.x;
    if (i < NN) g_rowstart[i] += g_bscan[i >> 10];
    if (i == 0) g_rowstart[NN] = EE;
}

__global__ void scatter_kernel(const void* __restrict__ ei, const float* __restrict__ ea) {
    int e = blockIdx.x * blockDim.x + threadIdx.x;
    if (e >= EE) return;
    int is64 = g_is64;
    int row = load_idx(ei, is64, e);
    int col = load_idx(ei, is64, EE + e);
    int idx = g_rowstart[row] + g_pos[e];
    g_edges[idx] = make_int2(col, __float_as_int(ea[e]));
}

// -------------------- fp32 -> bf16 hi/lo split of x --------------------
__global__ void convert_x(const float* __restrict__ x) {
    int i = blockIdx.x * blockDim.x + threadIdx.x;
    if (i >= NN * DD) return;
    float f = x[i];
    __nv_bfloat16 hi = __float2bfloat16(f);
    __nv_bfloat16 lo = __float2bfloat16(f - __bfloat162float(hi));
    g_xhi[i] = hi;
    g_xlo[i] = lo;
}

// -------------------- W -> W^T bf16 hi/lo (4 matrices) --------------------
__global__ void convert_w(const float* __restrict__ W0, const float* __restrict__ W1,
                          const float* __restrict__ W2, const float* __restrict__ W3) {
    int i = blockIdx.x * blockDim.x + threadIdx.x;
    if (i >= 4 * DD * DD) return;
    int w = i >> 14;
    int n = (i >> 7) & 127;
    int k = i & 127;
    const float* W = (w == 0) ? W0 : (w == 1) ? W1 : (w == 2) ? W2 : W3;
    float f = W[k * DD + n];                      // transpose: B[n][k] = W[k][n]
    __nv_bfloat16 hi = __float2bfloat16(f);
    __nv_bfloat16 lo = __float2bfloat16(f - __bfloat162float(hi));
    g_whi[i] = hi;
    g_wlo[i] = lo;
}

// -------------------- HMMA GEMM: C = (Ahi+Alo) @ (Bhi+Blo)^T + bias --------
// CTA tile 128(M) x 128(N) x 128(K). 8 warps (2x4), warp tile 64x32.
// bf16-split: D = Ahi*Bhi + Ahi*Blo + Alo*Bhi (lo*lo dropped, ~2^-18).
#define LDA 136                        // bf16 stride; 272B rows -> conflict-free ldmatrix
#define TILE_ELEMS (128 * LDA)
#define SME_BIAS_OFF (4 * TILE_ELEMS)
#define SME_TOT (4 * TILE_ELEMS * 2 + 512)

__global__ __launch_bounds__(256, 1)
void tgemm(const __nv_bfloat16* __restrict__ Ahi, const __nv_bfloat16* __restrict__ Alo,
           const __nv_bfloat16* __restrict__ Bhi, const __nv_bfloat16* __restrict__ Blo,
           const float* __restrict__ bias, float* __restrict__ C)
{
    extern __shared__ __nv_bfloat16 sm[];
    __nv_bfloat16* sAhi = sm;
    __nv_bfloat16* sAlo = sm + TILE_ELEMS;
    __nv_bfloat16* sBhi = sm + 2 * TILE_ELEMS;
    __nv_bfloat16* sBlo = sm + 3 * TILE_ELEMS;
    float* sbias = (float*)(sm + SME_BIAS_OFF);

    const int tid  = threadIdx.x;
    const int row0 = blockIdx.x * 128;

    const uint4 zero4 = make_uint4(0, 0, 0, 0);
#pragma unroll
    for (int t = tid; t < 2048; t += 256) {
        int r  = t >> 4;
        int c8 = (t & 15) << 3;
        bool aok = (row0 + r) < NN;
        uint4 va = aok ? *(const uint4*)(Ahi + (size_t)(row0 + r) * DD + c8) : zero4;
        uint4 vb = aok ? *(const uint4*)(Alo + (size_t)(row0 + r) * DD + c8) : zero4;
        *(uint4*)(sAhi + r * LDA + c8) = va;
        *(uint4*)(sAlo + r * LDA + c8) = vb;
        uint4 wa = *(const uint4*)(Bhi + (size_t)r * DD + c8);
        uint4 wb = *(const uint4*)(Blo + (size_t)r * DD + c8);
        *(uint4*)(sBhi + r * LDA + c8) = wa;
        *(uint4*)(sBlo + r * LDA + c8) = wb;
    }
    if (tid < 128) sbias[tid] = bias[tid];
    __syncthreads();

    const int wid  = tid >> 5;
    const int lane = tid & 31;
    const int wm = (wid >> 2) * 64;
    const int wn = (wid & 3) * 32;

    const int sub = lane >> 3;
    const int r8  = lane & 7;
    const int aRow = r8 + (sub & 1) * 8;
    const int aKof = (sub >> 1) * 8;
    const int bl  = lane & 15;
    const int bRow = bl & 7;
    const int bKof = (bl >> 3) * 8;

    const uint32_t smb = smem_u32(sm);
    const uint32_t aHiB = smb;
    const uint32_t bHiB = smb + 2 * TILE_ELEMS * 2;

    float acc[4][4][4];
#pragma unroll
    for (int mt = 0; mt < 4; mt++)
#pragma unroll
        for (int nt = 0; nt < 4; nt++)
#pragma unroll
            for (int j = 0; j < 4; j++) acc[mt][nt][j] = 0.0f;

#pragma unroll
    for (int ks = 0; ks < 8; ks++) {
        const int k0 = ks * 16;
        uint32_t bhi[4][2], blo[4][2];
#pragma unroll
        for (int nt = 0; nt < 4; nt++) {
            uint32_t off = (uint32_t)((wn + nt * 8 + bRow) * LDA + k0 + bKof) * 2;
            ldsm_x2(bhi[nt][0], bhi[nt][1], bHiB + off);
            ldsm_x2(blo[nt][0], blo[nt][1], bHiB + TILE_ELEMS * 2 + off);
        }
        uint32_t ahi[4][4], alo[4][4];
#pragma unroll
        for (int mt = 0; mt < 4; mt++) {
            uint32_t off = (uint32_t)((wm + mt * 16 + aRow) * LDA + k0 + aKof) * 2;
            ldsm_x4(ahi[mt][0], ahi[mt][1], ahi[mt][2], ahi[mt][3], aHiB + off);
            ldsm_x4(alo[mt][0], alo[mt][1], alo[mt][2], alo[mt][3],
                    aHiB + TILE_ELEMS * 2 + off);
        }
#pragma unroll
        for (int mt = 0; mt < 4; mt++)
#pragma unroll
            for (int nt = 0; nt < 4; nt++) {
                mma16816(acc[mt][nt], ahi[mt], bhi[nt]);
                mma16816(acc[mt][nt], ahi[mt], blo[nt]);
                mma16816(acc[mt][nt], alo[mt], bhi[nt]);
            }
    }

    const int g  = lane >> 2;
    const int t4 = lane & 3;
#pragma unroll
    for (int mt = 0; mt < 4; mt++) {
#pragma unroll
        for (int nt = 0; nt < 4; nt++) {
            int col = wn + nt * 8 + t4 * 2;
            float b0 = sbias[col], b1 = sbias[col + 1];
            int gr0 = row0 + wm + mt * 16 + g;
            if (gr0 < NN) {
                float2 o = make_float2(acc[mt][nt][0] + b0, acc[mt][nt][1] + b1);
                *(float2*)(C + (size_t)gr0 * DD + col) = o;
            }
            int gr1 = gr0 + 8;
            if (gr1 < NN) {
                float2 o = make_float2(acc[mt][nt][2] + b0, acc[mt][nt][3] + b1);
                *(float2*)(C + (size_t)gr1 * DD + col) = o;
            }
        }
    }
}

// -------------------- node pass: warp per node, register accumulation --------
// out[n] = sum_e exp(score_e) * V[col_e] / (sum_e exp(score_e) + 1e-8)
// Emitted directly as bf16 hi/lo (A operand of the final GEMM).
__global__ __launch_bounds__(256)
void node_pass()
{
    int n = (int)((blockIdx.x * (unsigned)blockDim.x + threadIdx.x) >> 5);
    if (n >= NN) return;
    const int lane = threadIdx.x & 31;

    const int beg = g_rowstart[n];
    const int end = g_rowstart[n + 1];

    const float4 q = ((const float4*)g_Q)[(size_t)n * 32 + lane];

    float4 accv = make_float4(0.f, 0.f, 0.f, 0.f);
    float  ssum = 0.0f;

#pragma unroll 2
    for (int i = beg; i < end; i++) {
        int2 epk = g_edges[i];               // warp-uniform broadcast
        int   c  = epk.x;
        float eav = __int_as_float(epk.y);

        float4 k = ((const float4*)g_K)[(size_t)c * 32 + lane];
        float d = q.x * k.x + q.y * k.y + q.z * k.z + q.w * k.w;
        d += __shfl_xor_sync(0xffffffffu, d, 1);
        d += __shfl_xor_sync(0xffffffffu, d, 2);   // per-head dot (4-lane groups)

        float sexp = __expf(d * 0.25f + eav);
        ssum += sexp;

        float4 v = ((const float4*)g_V)[(size_t)c * 32 + lane];
        accv.x += sexp * v.x;
        accv.y += sexp * v.y;
        accv.z += sexp * v.z;
        accv.w += sexp * v.w;
    }

    const float inv = 1.0f / (ssum + 1e-8f);       // ssum identical within head group
    float4 o = make_float4(accv.x * inv, accv.y * inv, accv.z * inv, accv.w * inv);

    __nv_bfloat16 h0 = __float2bfloat16(o.x), h1 = __float2bfloat16(o.y);
    __nv_bfloat16 h2 = __float2bfloat16(o.z), h3 = __float2bfloat16(o.w);
    __nv_bfloat16 l0 = __float2bfloat16(o.x - __bfloat162float(h0));
    __nv_bfloat16 l1 = __float2bfloat16(o.y - __bfloat162float(h1));
    __nv_bfloat16 l2 = __float2bfloat16(o.z - __bfloat162float(h2));
    __nv_bfloat16 l3 = __float2bfloat16(o.w - __bfloat162float(h3));

    uint2 whi = make_uint2(pack_bf2(h0, h1), pack_bf2(h2, h3));
    uint2 wlo = make_uint2(pack_bf2(l0, l1), pack_bf2(l2, l3));
    *(uint2*)(g_xhi + (size_t)n * DD + lane * 4) = whi;
    *(uint2*)(g_xlo + (size_t)n * DD + lane * 4) = wlo;
}

// -------------------- launch --------------------
extern "C" void kernel_launch(void* const* d_in, const int* in_sizes, int n_in,
                              void* d_out, int out_size)
{
    const float* x  = (const float*)d_in[0];
    const void*  ei = d_in[1];
    const float* ea = (const float*)d_in[2];
    const float* Wq = (const float*)d_in[3];
    const float* bq = (const float*)d_in[4];
    const float* Wk = (const float*)d_in[5];
    const float* bk = (const float*)d_in[6];
    const float* Wv = (const float*)d_in[7];
    const float* bv = (const float*)d_in[8];
    const float* Wo = (const float*)d_in[9];
    const float* bo = (const float*)d_in[10];
    float* out = (float*)d_out;

    static int smem_set = 0;
    if (!smem_set) {
        cudaFuncSetAttribute(tgemm, cudaFuncAttributeMaxDynamicSharedMemorySize, SME_TOT);
        smem_set = 1;
    }

    __nv_bfloat16 *xhi, *xlo, *whi, *wlo;
    float *Qp, *Kp, *Vp;
    cudaGetSymbolAddress((void**)&xhi, g_xhi);
    cudaGetSymbolAddress((void**)&xlo, g_xlo);
    cudaGetSymbolAddress((void**)&whi, g_whi);
    cudaGetSymbolAddress((void**)&wlo, g_wlo);
    cudaGetSymbolAddress((void**)&Qp, g_Q);
    cudaGetSymbolAddress((void**)&Kp, g_K);
    cudaGetSymbolAddress((void**)&Vp, g_V);

    const int gemm_blocks = (NN + 127) / 128;

    probe_zero<<<(NN + 255) / 256, 256>>>(ei);
    convert_x<<<(NN * DD + 255) / 256, 256>>>(x);
    convert_w<<<(4 * DD * DD + 255) / 256, 256>>>(Wq, Wk, Wv, Wo);

    // CSR build
    hist_kernel<<<(EE + 255) / 256, 256>>>(ei);
    scan1_kernel<<<49, 1024>>>();
    scan2_kernel<<<1, 64>>>();
    scan3_kernel<<<(NN + 255) / 256, 256>>>();
    scatter_kernel<<<(EE + 255) / 256, 256>>>(ei, ea);

    // Projections
    tgemm<<<gemm_blocks, 256, SME_TOT>>>(xhi, xlo, whi + 0 * DD * DD, wlo + 0 * DD * DD, bq, Qp);
    tgemm<<<gemm_blocks, 256, SME_TOT>>>(xhi, xlo, whi + 1 * DD * DD, wlo + 1 * DD * DD, bk, Kp);
    tgemm<<<gemm_blocks, 256, SME_TOT>>>(xhi, xlo, whi + 2 * DD * DD, wlo + 2 * DD * DD, bv, Vp);

    // Attention (writes bf16 hi/lo A operand for final GEMM)
    node_pass<<<(NN * 32 + 255) / 256, 256>>>();

    // Output projection
    tgemm<<<gemm_blocks, 256, SME_TOT>>>(xhi, xlo, whi + 3 * DD * DD, wlo + 3 * DD * DD, bo, out);
}

// round 13
// speedup vs baseline: 2.9767x; 1.4457x over previous
#include <cuda_runtime.h>
#include <cuda_fp16.h>
#include <math.h>
#include <stdint.h>

#define NN 50000
#define EE 600000
#define DD 128
#define HH 8
// SCALE = sqrt(DH) = 4 -> multiply by 0.25f

// -------------------- scratch (device globals; no allocation) --------------------
__device__ __half g_Qh[(size_t)NN * DD];
__device__ __half g_Kh[(size_t)NN * DD];
__device__ __half g_Vh[(size_t)NN * DD];
__device__ __half g_xh[(size_t)NN * DD];     // A operand (x, later attn-out)
__device__ __half g_wh[4 * DD * DD];         // W^T fp16: [mat][n][k]
__device__ int   g_counts[NN];
__device__ int   g_pos[EE];
__device__ int   g_rowstart[NN + 1];
__device__ int   g_bsum[64];
__device__ int   g_bscan[64];
__device__ int2  g_edges[EE];                // {col, ea bits} grouped by row
__device__ int   g_is64;

// -------------------- helpers --------------------
__device__ __forceinline__ uint32_t smem_u32(const void* p) {
    uint32_t a;
    asm("{ .reg .u64 t; cvta.to.shared.u64 t, %1; cvt.u32.u64 %0, t; }" : "=r"(a) : "l"(p));
    return a;
}
__device__ __forceinline__ int load_idx(const void* ei, int is64, int pos) {
    if (is64) return (int)((const long long*)ei)[pos];
    return ((const int*)ei)[pos];
}
__device__ __forceinline__ void ldsm_x4(uint32_t& r0, uint32_t& r1, uint32_t& r2, uint32_t& r3,
                                        uint32_t addr) {
    asm volatile("ldmatrix.sync.aligned.m8n8.x4.shared.b16 {%0,%1,%2,%3}, [%4];"
                 : "=r"(r0), "=r"(r1), "=r"(r2), "=r"(r3) : "r"(addr));
}
__device__ __forceinline__ void ldsm_x2(uint32_t& r0, uint32_t& r1, uint32_t addr) {
    asm volatile("ldmatrix.sync.aligned.m8n8.x2.shared.b16 {%0,%1}, [%2];"
                 : "=r"(r0), "=r"(r1) : "r"(addr));
}
__device__ __forceinline__ void mma16816h(float* d, const uint32_t* a, const uint32_t* b) {
    asm volatile("mma.sync.aligned.m16n8k16.row.col.f32.f16.f16.f32 "
                 "{%0,%1,%2,%3}, {%4,%5,%6,%7}, {%8,%9}, {%0,%1,%2,%3};"
                 : "+f"(d[0]), "+f"(d[1]), "+f"(d[2]), "+f"(d[3])
                 : "r"(a[0]), "r"(a[1]), "r"(a[2]), "r"(a[3]), "r"(b[0]), "r"(b[1]));
}

// -------------------- probe dtype + zero counts --------------------
__global__ void probe_zero(const void* ei) {
    int i = blockIdx.x * blockDim.x + threadIdx.x;
    if (i == 0) {
        const long long* p = (const long long*)ei;
        int ok = 1;
        for (int t = 0; t < 64; t++) {
            long long v = p[t];
            if (v < 0 || v >= NN) { ok = 0; break; }
        }
        g_is64 = ok;
    }
    if (i < NN) g_counts[i] = 0;
}

// -------------------- CSR build --------------------
__global__ void hist_kernel(const void* __restrict__ ei) {
    int e = blockIdx.x * blockDim.x + threadIdx.x;
    if (e >= EE) return;
    int row = load_idx(ei, g_is64, e);
    g_pos[e] = atomicAdd(&g_counts[row], 1);
}

__global__ __launch_bounds__(1024) void scan1_kernel() {
    __shared__ int s[1024];
    int tid = threadIdx.x;
    int gid = blockIdx.x * 1024 + tid;
    int v = (gid < NN) ? g_counts[gid] : 0;
    s[tid] = v;
    __syncthreads();
#pragma unroll
    for (int off = 1; off < 1024; off <<= 1) {
        int t = (tid >= off) ? s[tid - off] : 0;
        __syncthreads();
        s[tid] += t;
        __syncthreads();
    }
    if (gid < NN) g_rowstart[gid] = s[tid] - v;    // exclusive within block
    if (tid == 1023) g_bsum[blockIdx.x] = s[1023];
}

__global__ void scan2_kernel() {
    __shared__ int s[64];
    int tid = threadIdx.x;
    int v = (tid < 49) ? g_bsum[tid] : 0;
    s[tid] = v;
    __syncthreads();
#pragma unroll
    for (int off = 1; off < 64; off <<= 1) {
        int t = (tid >= off) ? s[tid - off] : 0;
        __syncthreads();
        s[tid] += t;
        __syncthreads();
    }
    g_bscan[tid] = s[tid] - v;
}

__global__ void scan3_kernel() {
    int i = blockIdx.x * blockDim.x + threadIdx.x;
    if (i < NN) g_rowstart[i] += g_bscan[i >> 10];
    if (i == 0) g_rowstart[NN] = EE;
}

__global__ void scatter_kernel(const void* __restrict__ ei, const float* __restrict__ ea) {
    int e = blockIdx.x * blockDim.x + threadIdx.x;
    if (e >= EE) return;
    int is64 = g_is64;
    int row = load_idx(ei, is64, e);
    int col = load_idx(ei, is64, EE + e);
    int idx = g_rowstart[row] + g_pos[e];
    g_edges[idx] = make_int2(col, __float_as_int(ea[e]));
}

// -------------------- fp32 -> fp16 conversions --------------------
__global__ void convert_x(const float* __restrict__ x) {
    int i = blockIdx.x * blockDim.x + threadIdx.x;
    if (i >= NN * DD) return;
    g_xh[i] = __float2half_rn(x[i]);
}

__global__ void convert_w(const float* __restrict__ W0, const float* __restrict__ W1,
                          const float* __restrict__ W2, const float* __restrict__ W3) {
    int i = blockIdx.x * blockDim.x + threadIdx.x;
    if (i >= 4 * DD * DD) return;
    int w = i >> 14;
    int n = (i >> 7) & 127;
    int k = i & 127;
    const float* W = (w == 0) ? W0 : (w == 1) ? W1 : (w == 2) ? W2 : W3;
    g_wh[i] = __float2half_rn(W[k * DD + n]);    // transpose: B[n][k] = W[k][n]
}

// -------------------- fp16 HMMA GEMM: C = A @ W^T + bias --------------------
// CTA tile 128(M) x 128(N) x 128(K), single fp16 chain. 8 warps (2x4), 64x32 each.
// fused=1: grid.y in {0,1,2} selects {Wq->Qh, Wk->Kh, Wv->Vh}, fp16 output.
// fused=0: single matrix, fp32 output to Cf.
#define LDA 136
#define TILE_ELEMS (128 * LDA)                 // halves
#define SME_BIAS_OFF (2 * TILE_ELEMS)
#define SME_TOT (2 * TILE_ELEMS * 2 + 512)     // ~70 KB

__global__ __launch_bounds__(256, 2)
void tgemm(const __half* __restrict__ A,
           const float* __restrict__ b0v, const float* __restrict__ b1v,
           const float* __restrict__ b2v,
           float* __restrict__ Cf, int fused)
{
    extern __shared__ __half sm[];
    __half* sA = sm;
    __half* sB = sm + TILE_ELEMS;
    float* sbias = (float*)(sm + SME_BIAS_OFF);

    const int mat  = fused ? blockIdx.y : 3;
    const __half* B = g_wh + (size_t)mat * DD * DD;
    const float* bias = fused ? (blockIdx.y == 0 ? b0v : blockIdx.y == 1 ? b1v : b2v) : b0v;
    __half* Ch = fused ? (blockIdx.y == 0 ? g_Qh : blockIdx.y == 1 ? g_Kh : g_Vh) : nullptr;

    const int tid  = threadIdx.x;
    const int row0 = blockIdx.x * 128;

    const uint4 zero4 = make_uint4(0, 0, 0, 0);
#pragma unroll
    for (int t = tid; t < 2048; t += 256) {
        int r  = t >> 4;
        int c8 = (t & 15) << 3;
        bool aok = (row0 + r) < NN;
        uint4 va = aok ? *(const uint4*)(A + (size_t)(row0 + r) * DD + c8) : zero4;
        *(uint4*)(sA + r * LDA + c8) = va;
        uint4 wb = *(const uint4*)(B + (size_t)r * DD + c8);
        *(uint4*)(sB + r * LDA + c8) = wb;
    }
    if (tid < 128) sbias[tid] = bias[tid];
    __syncthreads();

    const int wid  = tid >> 5;
    const int lane = tid & 31;
    const int wm = (wid >> 2) * 64;
    const int wn = (wid & 3) * 32;

    const int sub = lane >> 3;
    const int r8  = lane & 7;
    const int aRow = r8 + (sub & 1) * 8;
    const int aKof = (sub >> 1) * 8;
    const int bl  = lane & 15;
    const int bRow = bl & 7;
    const int bKof = (bl >> 3) * 8;

    const uint32_t smb = smem_u32(sm);
    const uint32_t aB = smb;
    const uint32_t bB = smb + TILE_ELEMS * 2;

    float acc[4][4][4];
#pragma unroll
    for (int mt = 0; mt < 4; mt++)
#pragma unroll
        for (int nt = 0; nt < 4; nt++)
#pragma unroll
            for (int j = 0; j < 4; j++) acc[mt][nt][j] = 0.0f;

#pragma unroll
    for (int ks = 0; ks < 8; ks++) {
        const int k0 = ks * 16;
        uint32_t bf[4][2];
#pragma unroll
        for (int nt = 0; nt < 4; nt++) {
            uint32_t off = (uint32_t)((wn + nt * 8 + bRow) * LDA + k0 + bKof) * 2;
            ldsm_x2(bf[nt][0], bf[nt][1], bB + off);
        }
        uint32_t af[4][4];
#pragma unroll
        for (int mt = 0; mt < 4; mt++) {
            uint32_t off = (uint32_t)((wm + mt * 16 + aRow) * LDA + k0 + aKof) * 2;
            ldsm_x4(af[mt][0], af[mt][1], af[mt][2], af[mt][3], aB + off);
        }
#pragma unroll
        for (int mt = 0; mt < 4; mt++)
#pragma unroll
            for (int nt = 0; nt < 4; nt++)
                mma16816h(acc[mt][nt], af[mt], bf[nt]);
    }

    const int g  = lane >> 2;
    const int t4 = lane & 3;
#pragma unroll
    for (int mt = 0; mt < 4; mt++) {
#pragma unroll
        for (int nt = 0; nt < 4; nt++) {
            int col = wn + nt * 8 + t4 * 2;
            float b0 = sbias[col], b1 = sbias[col + 1];
            int gr0 = row0 + wm + mt * 16 + g;
            int gr1 = gr0 + 8;
            if (fused) {
                if (gr0 < NN)
                    *(__half2*)(Ch + (size_t)gr0 * DD + col) =
                        __floats2half2_rn(acc[mt][nt][0] + b0, acc[mt][nt][1] + b1);
                if (gr1 < NN)
                    *(__half2*)(Ch + (size_t)gr1 * DD + col) =
                        __floats2half2_rn(acc[mt][nt][2] + b0, acc[mt][nt][3] + b1);
            } else {
                if (gr0 < NN)
                    *(float2*)(Cf + (size_t)gr0 * DD + col) =
                        make_float2(acc[mt][nt][0] + b0, acc[mt][nt][1] + b1);
                if (gr1 < NN)
                    *(float2*)(Cf + (size_t)gr1 * DD + col) =
                        make_float2(acc[mt][nt][2] + b0, acc[mt][nt][3] + b1);
            }
        }
    }
}

// -------------------- node pass: warp per node, register accumulation --------
// out[n] = sum_e exp(score_e) * V[col_e] / (sum_e exp(score_e) + 1e-8)
// Q/K/V in fp16 (half gather traffic); emits fp16 A operand for final GEMM.
__global__ __launch_bounds__(256)
void node_pass()
{
    int n = (int)((blockIdx.x * (unsigned)blockDim.x + threadIdx.x) >> 5);
    if (n >= NN) return;
    const int lane = threadIdx.x & 31;

    const int beg = g_rowstart[n];
    const int end = g_rowstart[n + 1];

    // Q for this node: lane covers dims lane*4 .. lane*4+3
    uint2 qp = *(const uint2*)(g_Qh + (size_t)n * DD + lane * 4);
    float2 q01 = __half22float2(*(__half2*)&qp.x);
    float2 q23 = __half22float2(*(__half2*)&qp.y);

    float4 accv = make_float4(0.f, 0.f, 0.f, 0.f);
    float  ssum = 0.0f;

#pragma unroll 2
    for (int i = beg; i < end; i++) {
        int2 epk = g_edges[i];                     // warp-uniform broadcast
        int   c  = epk.x;
        float eav = __int_as_float(epk.y);

        uint2 kp = *(const uint2*)(g_Kh + (size_t)c * DD + lane * 4);
        float2 k01 = __half22float2(*(__half2*)&kp.x);
        float2 k23 = __half22float2(*(__half2*)&kp.y);
        float d = q01.x * k01.x + q01.y * k01.y + q23.x * k23.x + q23.y * k23.y;
        d += __shfl_xor_sync(0xffffffffu, d, 1);
        d += __shfl_xor_sync(0xffffffffu, d, 2);   // per-head dot (4-lane groups)

        float sexp = __expf(d * 0.25f + eav);
        ssum += sexp;

        uint2 vp = *(const uint2*)(g_Vh + (size_t)c * DD + lane * 4);
        float2 v01 = __half22float2(*(__half2*)&vp.x);
        float2 v23 = __half22float2(*(__half2*)&vp.y);
        accv.x += sexp * v01.x;
        accv.y += sexp * v01.y;
        accv.z += sexp * v23.x;
        accv.w += sexp * v23.y;
    }

    const float inv = 1.0f / (ssum + 1e-8f);       // ssum identical within head group
    uint2 o;
    *(__half2*)&o.x = __floats2half2_rn(accv.x * inv, accv.y * inv);
    *(__half2*)&o.y = __floats2half2_rn(accv.z * inv, accv.w * inv);
    *(uint2*)(g_xh + (size_t)n * DD + lane * 4) = o;
}

// -------------------- launch --------------------
extern "C" void kernel_launch(void* const* d_in, const int* in_sizes, int n_in,
                              void* d_out, int out_size)
{
    const float* x  = (const float*)d_in[0];
    const void*  ei = d_in[1];
    const float* ea = (const float*)d_in[2];
    const float* Wq = (const float*)d_in[3];
    const float* bq = (const float*)d_in[4];
    const float* Wk = (const float*)d_in[5];
    const float* bk = (const float*)d_in[6];
    const float* Wv = (const float*)d_in[7];
    const float* bv = (const float*)d_in[8];
    const float* Wo = (const float*)d_in[9];
    const float* bo = (const float*)d_in[10];
    float* out = (float*)d_out;

    static int smem_set = 0;
    if (!smem_set) {
        cudaFuncSetAttribute(tgemm, cudaFuncAttributeMaxDynamicSharedMemorySize, SME_TOT);
        smem_set = 1;
    }

    __half* xh;
    cudaGetSymbolAddress((void**)&xh, g_xh);

    const int gemm_blocks = (NN + 127) / 128;

    probe_zero<<<(NN + 255) / 256, 256>>>(ei);
    convert_x<<<(NN * DD + 255) / 256, 256>>>(x);
    convert_w<<<(4 * DD * DD + 255) / 256, 256>>>(Wq, Wk, Wv, Wo);

    // CSR build
    hist_kernel<<<(EE + 255) / 256, 256>>>(ei);
    scan1_kernel<<<49, 1024>>>();
    scan2_kernel<<<1, 64>>>();
    scan3_kernel<<<(NN + 255) / 256, 256>>>();
    scatter_kernel<<<(EE + 255) / 256, 256>>>(ei, ea);

    // Fused Q,K,V projections: grid (391, 3), fp16 outputs
    tgemm<<<dim3(gemm_blocks, 3), 256, SME_TOT>>>(xh, bq, bk, bv, nullptr, 1);

    // Attention (writes fp16 A operand for final GEMM)
    node_pass<<<(NN * 32 + 255) / 256, 256>>>();

    // Output projection (fp32 out)
    tgemm<<<dim3(gemm_blocks, 1), 256, SME_TOT>>>(xh, bo, nullptr, nullptr, out, 0);
}